// round 14
// baseline (speedup 1.0000x reference)
#include <cuda_runtime.h>

typedef unsigned long long ull;

#define TSX     32          // tile width
#define TSY     64          // tile height
#define HALO    5
#define KW      11
#define RNX     42          // TSX + 2*HALO
#define RNY     74          // TSY + 2*HALO
#define PPX     46          // sxy pitch in (u,v) pairs — EVEN so ull-index parity
                            // depends only on hj0 (16B alignment per group);
                            // lane stride 92 words = 28 mod 32: quarter-warp
                            // LDS.128 phases conflict-free
#define HP      33          // h-buffer pitch in float4
#define IMH     2048
#define IMW     2048
#define NCH     3
#define NTHREADS 256
#define GX      64          // 2048 / TSX
#define GY      32          // 2048 / TSY
#define NBLK    (GX*GY)

#define C1 1.0e-4f
#define C2 9.0e-4f

// per-channel smem layout (floats)
#define OFS_SXY  0                              // RNY*PPX ull = 6808 floats
#define OFS_H    (RNY*PPX*2)                    // 6808
#define SMEM_FLOATS (OFS_H + RNY*HP*4)          // +9768 = 16576 (66304 B)

#define WIDX(k) ((k) <= 5 ? (k) : (10 - (k)))   // symmetric Gaussian taps

__device__ float g_partial[NBLK];
__device__ unsigned int g_flag;   // zero-init; last block resets it

__device__ __forceinline__ ull pack2(float lo, float hi) {
    ull r; asm("mov.b64 %0,{%1,%2};" : "=l"(r) : "f"(lo), "f"(hi)); return r;
}
__device__ __forceinline__ float2 unpack2(ull v) {
    float2 r; asm("mov.b64 {%0,%1},%2;" : "=f"(r.x), "=f"(r.y) : "l"(v)); return r;
}
__device__ __forceinline__ ull fma2(ull a, ull b, ull c) {
    ull d; asm("fma.rn.f32x2 %0,%1,%2,%3;" : "=l"(d) : "l"(a), "l"(b), "l"(c)); return d;
}
__device__ __forceinline__ ull mul2(ull a, ull b) {
    ull d; asm("mul.rn.f32x2 %0,%1,%2;" : "=l"(d) : "l"(a), "l"(b)); return d;
}

// apply tap T (compile-time) of the 11-wide horizontal block
#define APPLY_TAP(T, VUV) do {                                         \
    ull _vss = mul2((VUV), (VUV));                                     \
    _Pragma("unroll")                                                  \
    for (int o = 0; o < 11; o++) {                                     \
        int k = (T) - o;                                               \
        if (k >= 0 && k < KW) {                                        \
            auv[o] = fma2(wwr[WIDX(k)], (VUV), auv[o]);                \
            ass[o] = fma2(wwr[WIDX(k)], _vss, ass[o]);                 \
        }                                                              \
    }                                                                  \
} while (0)

// -------- load: warp-per-row, division-free; interior CTAs skip all checks ---
__device__ __forceinline__ void load_interior(
    const float* __restrict__ img1, const float* __restrict__ img2,
    float* __restrict__ sxyF, int c, int row0, int col0, int wid, int lane)
{
    const float* b1 = img1 + (row0 * IMW + col0) * NCH + c;
    const float* b2 = img2 + (row0 * IMW + col0) * NCH + c;
    for (int r = wid; r < RNY; r += 8) {
        int roff = r * (IMW * NCH);
        float x = b1[roff + lane * NCH];
        float y = b2[roff + lane * NCH];
        ((float2*)sxyF)[r * PPX + lane] = make_float2(x + y, x - y);
        if (lane < RNX - 32) {
            int p = 32 + lane;
            float x2 = b1[roff + p * NCH];
            float y2 = b2[roff + p * NCH];
            ((float2*)sxyF)[r * PPX + p] = make_float2(x2 + y2, x2 - y2);
        }
    }
}

__device__ __forceinline__ void load_border(
    const float* __restrict__ img1, const float* __restrict__ img2,
    float* __restrict__ sxyF, int c, int row0, int col0, int wid, int lane)
{
    for (int r = wid; r < RNY; r += 8) {
        int gr = row0 + r;
        bool rok = (gr >= 0 && gr < IMH);
        #pragma unroll
        for (int s = 0; s < 2; s++) {
            int p = s * 32 + lane;
            if (p < RNX) {
                int gc = col0 + p;
                float v1 = 0.f, v2 = 0.f;
                if (rok && gc >= 0 && gc < IMW) {
                    int off = (gr * IMW + gc) * NCH + c;
                    v1 = img1[off];
                    v2 = img2[off];
                }
                ((float2*)sxyF)[r * PPX + p] = make_float2(v1 + v2, v1 - v2);
            }
        }
    }
}

__global__ __launch_bounds__(NTHREADS, 3) void ssim_tile_kernel(
    const float* __restrict__ img1,
    const float* __restrict__ img2,
    const float* __restrict__ window,
    float* __restrict__ out)
{
    extern __shared__ float smem[];
    float* sxyF = smem + OFS_SXY;                // (u,v) pairs, one channel
    float* hF   = smem + OFS_H;                  // (U,V,Su,Sv) float4 per column

    const int tid  = threadIdx.x;
    const int wid  = tid >> 5;
    const int lane = tid & 31;

    // ---- separable taps (symmetric): g_k = w2d[5][k] / sqrt(w2d[5][5]), k<=5
    ull wwr[6];
    {
        float g5 = sqrtf(window[5 * KW + 5]);
        #pragma unroll
        for (int k = 0; k < 6; k++) {
            float w = window[5 * KW + k] / g5;
            wwr[k] = pack2(w, w);
        }
    }

    const int row0 = (int)blockIdx.y * TSY - HALO;
    const int col0 = (int)blockIdx.x * TSX - HALO;
    const bool interior = (row0 >= 0) && (row0 + RNY <= IMH) &&
                          (col0 >= 0) && (col0 + RNX <= IMW);

    // horizontal mapping: 222 items = 3 col-groups x 74 rows, single wave
    const int hg  = (tid >= 148) ? 2 : (tid >= 74 ? 1 : 0);
    const int hr  = tid - hg * 74;
    const int hj0 = hg * 11;

    float lsum = 0.f;

    for (int c = 0; c < NCH; c++) {
        // ---------- per-channel load ----------
        if (interior)
            load_interior(img1, img2, sxyF, c, row0, col0, wid, lane);
        else
            load_border(img1, img2, sxyF, c, row0, col0, wid, lane);
        __syncthreads();

        // ---------- horizontal pass: uniform 11-wide, single full wave --------
        // smem reads vectorized to LDS.128. PPX is even, so the ull-index
        // hr*PPX + hj0 has parity of hj0: groups 0/2 start 16B-aligned
        // (10x128 + 1x64), group 1 starts odd (1x64 + 10x128).
        // group 2 computes 11 outputs but stores only 10 (col 32 discarded;
        // its window reads the never-written pitch word col 42, which only
        // feeds the discarded accumulator).
        if (tid < 222) {
            const ull* puv = (const ull*)sxyF + hr * PPX + hj0;

            ull auv[11], ass[11];
            #pragma unroll
            for (int o = 0; o < 11; o++) { auv[o] = 0; ass[o] = 0; }

            if (hg == 1) {                        // odd start: 1x64 + 10x128
                { ull v = puv[0]; APPLY_TAP(0, v); }
                #pragma unroll
                for (int t2 = 1; t2 < 21; t2 += 2) {
                    ulonglong2 vv = *reinterpret_cast<const ulonglong2*>(puv + t2);
                    APPLY_TAP(t2,     vv.x);
                    APPLY_TAP(t2 + 1, vv.y);
                }
            } else {                              // even start: 10x128 + 1x64
                #pragma unroll
                for (int t2 = 0; t2 < 20; t2 += 2) {
                    ulonglong2 vv = *reinterpret_cast<const ulonglong2*>(puv + t2);
                    APPLY_TAP(t2,     vv.x);
                    APPLY_TAP(t2 + 1, vv.y);
                }
                { ull v = puv[20]; APPLY_TAP(20, v); }
            }

            float4* dst = (float4*)hF + hr * HP + hj0;
            #pragma unroll
            for (int o = 0; o < 11; o++) {
                if (o < 10 || hg < 2) {
                    float2 a = unpack2(auv[o]);
                    float2 b = unpack2(ass[o]);
                    dst[o] = make_float4(a.x, a.y, b.x, b.y);
                }
            }
        }
        __syncthreads();   // sxy reads done; h writes visible

        // ---------- vertical pass: exact single wave (32 cols x 8 warps) ------
        {
            int tx  = lane;                       // column 0..31
            int ty0 = wid << 3;                   // stack base row 0..56
            ull aU[8], aS[8];
            #pragma unroll
            for (int o = 0; o < 8; o++) { aU[o] = 0; aS[o] = 0; }

            #pragma unroll
            for (int t = 0; t < 18; t++) {
                int r = ty0 + t;
                float4 h = ((const float4*)hF)[r * HP + tx];
                ull huv = pack2(h.x, h.y);
                ull hss = pack2(h.z, h.w);
                #pragma unroll
                for (int o = 0; o < 8; o++) {
                    int k = t - o;
                    if (k >= 0 && k < KW) {
                        aU[o] = fma2(wwr[WIDX(k)], huv, aU[o]);
                        aS[o] = fma2(wwr[WIDX(k)], hss, aS[o]);
                    }
                }
            }
            #pragma unroll
            for (int o = 0; o < 8; o++) {
                float2 uv = unpack2(aU[o]);      // U = mu1+mu2, V = mu1-mu2
                float2 ss = unpack2(aS[o]);      // Su = E[u^2], Sv = E[v^2]
                float U2 = uv.x * uv.x;
                float V2 = uv.y * uv.y;
                float A  = ss.x - U2;            // = s1+s2+2*s12 (x2 scale)
                float B  = ss.y - V2;            // = s1+s2-2*s12 (x2 scale)
                float num = fmaf(0.5f, U2 - V2, C1) * fmaf(0.5f, A - B, C2);
                float den = fmaf(0.5f, U2 + V2, C1) * fmaf(0.5f, A + B, C2);
                lsum += __fdividef(num, den);
            }
        }
        __syncthreads();   // h reads done before next channel overwrites sxy/h
    }

    // ---------- block reduction (8 warps) ----------
    #pragma unroll
    for (int s = 16; s > 0; s >>= 1)
        lsum += __shfl_xor_sync(0xffffffffu, lsum, s);
    __shared__ float red[8];
    if (lane == 0) red[wid] = lsum;
    __syncthreads();
    if (tid == 0) {
        float bs = 0.f;
        #pragma unroll
        for (int i = 0; i < 8; i++) bs += red[i];
        g_partial[blockIdx.y * GX + blockIdx.x] = bs;
    }

    // ---------- last-block finalize (no second launch) ----------
    __shared__ bool amLast;
    __threadfence();
    if (tid == 0) {
        unsigned int n = atomicAdd(&g_flag, 1u);
        amLast = (n == (unsigned)(NBLK - 1));
    }
    __syncthreads();
    if (amLast) {
        double s = 0.0;
        for (int i = tid; i < NBLK; i += NTHREADS)
            s += (double)g_partial[i];
        #pragma unroll
        for (int sft = 16; sft > 0; sft >>= 1)
            s += __shfl_xor_sync(0xffffffffu, s, sft);
        __shared__ double rd[8];
        if (lane == 0) rd[wid] = s;
        __syncthreads();
        if (tid == 0) {
            double t = 0.0;
            #pragma unroll
            for (int i = 0; i < 8; i++) t += rd[i];
            out[0] = (float)(1.0 - t / ((double)IMH * IMW * NCH));
            g_flag = 0;                 // reset for next graph replay
        }
    }
}

extern "C" void kernel_launch(void* const* d_in, const int* in_sizes, int n_in,
                              void* d_out, int out_size)
{
    const float* img1 = (const float*)d_in[0];
    const float* img2 = (const float*)d_in[1];
    const float* win  = (const float*)d_in[2];
    float* out = (float*)d_out;
    (void)in_sizes; (void)n_in; (void)out_size;

    const size_t SMEM = (size_t)SMEM_FLOATS * sizeof(float);   // 66304 B
    cudaFuncSetAttribute(ssim_tile_kernel,
                         cudaFuncAttributeMaxDynamicSharedMemorySize, (int)SMEM);

    dim3 grid(GX, GY);
    ssim_tile_kernel<<<grid, NTHREADS, SMEM>>>(img1, img2, win, out);
}

// round 15
// speedup vs baseline: 1.1177x; 1.1177x over previous
#include <cuda_runtime.h>

typedef unsigned long long ull;

#define TSX     32          // tile width
#define TSY     64          // tile height
#define HALO    5
#define KW      11
#define RNX     42          // TSX + 2*HALO
#define RNY     74          // TSY + 2*HALO
#define PPX     43          // sxy pitch in (u,v) pairs (ull)
#define HP      33          // h-buffer pitch in 16B elements
#define IMH     2048
#define IMW     2048
#define NCH     3
#define NTHREADS 256
#define GX      64          // 2048 / TSX
#define GY      32          // 2048 / TSY
#define NBLK    (GX*GY)

#define C1 1.0e-4f
#define C2 9.0e-4f

// per-channel smem layout (floats)
#define OFS_SXY  0                              // RNY*PPX ull = 6364 floats
#define OFS_H    (RNY*PPX*2)                    // 6364 floats = 25456 B (16B-aligned)
#define SMEM_FLOATS (OFS_H + RNY*HP*4)          // +9768 = 16132 (64528 B)

#define WIDX(k) ((k) <= 5 ? (k) : (10 - (k)))   // symmetric Gaussian taps

__device__ float g_partial[NBLK];
__device__ unsigned int g_flag;   // zero-init; last block resets it

__device__ __forceinline__ ull pack2(float lo, float hi) {
    ull r; asm("mov.b64 %0,{%1,%2};" : "=l"(r) : "f"(lo), "f"(hi)); return r;
}
__device__ __forceinline__ float2 unpack2(ull v) {
    float2 r; asm("mov.b64 {%0,%1},%2;" : "=f"(r.x), "=f"(r.y) : "l"(v)); return r;
}
__device__ __forceinline__ ull fma2(ull a, ull b, ull c) {
    ull d; asm("fma.rn.f32x2 %0,%1,%2,%3;" : "=l"(d) : "l"(a), "l"(b), "l"(c)); return d;
}
__device__ __forceinline__ ull mul2(ull a, ull b) {
    ull d; asm("mul.rn.f32x2 %0,%1,%2;" : "=l"(d) : "l"(a), "l"(b)); return d;
}

// -------- load: warp-per-row, division-free; interior CTAs skip all checks ---
__device__ __forceinline__ void load_interior(
    const float* __restrict__ img1, const float* __restrict__ img2,
    float* __restrict__ sxyF, int c, int row0, int col0, int wid, int lane)
{
    const float* b1 = img1 + (row0 * IMW + col0) * NCH + c;
    const float* b2 = img2 + (row0 * IMW + col0) * NCH + c;
    for (int r = wid; r < RNY; r += 8) {
        int roff = r * (IMW * NCH);
        float x = b1[roff + lane * NCH];
        float y = b2[roff + lane * NCH];
        ((float2*)sxyF)[r * PPX + lane] = make_float2(x + y, x - y);
        if (lane < RNX - 32) {
            int p = 32 + lane;
            float x2 = b1[roff + p * NCH];
            float y2 = b2[roff + p * NCH];
            ((float2*)sxyF)[r * PPX + p] = make_float2(x2 + y2, x2 - y2);
        }
    }
}

__device__ __forceinline__ void load_border(
    const float* __restrict__ img1, const float* __restrict__ img2,
    float* __restrict__ sxyF, int c, int row0, int col0, int wid, int lane)
{
    for (int r = wid; r < RNY; r += 8) {
        int gr = row0 + r;
        bool rok = (gr >= 0 && gr < IMH);
        #pragma unroll
        for (int s = 0; s < 2; s++) {
            int p = s * 32 + lane;
            if (p < RNX) {
                int gc = col0 + p;
                float v1 = 0.f, v2 = 0.f;
                if (rok && gc >= 0 && gc < IMW) {
                    int off = (gr * IMW + gc) * NCH + c;
                    v1 = img1[off];
                    v2 = img2[off];
                }
                ((float2*)sxyF)[r * PPX + p] = make_float2(v1 + v2, v1 - v2);
            }
        }
    }
}

__global__ __launch_bounds__(NTHREADS, 3) void ssim_tile_kernel(
    const float* __restrict__ img1,
    const float* __restrict__ img2,
    const float* __restrict__ window,
    float* __restrict__ out)
{
    extern __shared__ float smem[];
    float* sxyF = smem + OFS_SXY;                // (u,v) pairs, one channel
    ulonglong2* hP = (ulonglong2*)(smem + OFS_H); // {(U,V),(Su,Sv)} 16B elements

    const int tid  = threadIdx.x;
    const int wid  = tid >> 5;
    const int lane = tid & 31;

    // ---- separable taps (symmetric): g_k = w2d[5][k] / sqrt(w2d[5][5]), k<=5
    ull wwr[6];
    {
        float g5 = sqrtf(window[5 * KW + 5]);
        #pragma unroll
        for (int k = 0; k < 6; k++) {
            float w = window[5 * KW + k] / g5;
            wwr[k] = pack2(w, w);
        }
    }

    const int row0 = (int)blockIdx.y * TSY - HALO;
    const int col0 = (int)blockIdx.x * TSX - HALO;
    const bool interior = (row0 >= 0) && (row0 + RNY <= IMH) &&
                          (col0 >= 0) && (col0 + RNX <= IMW);

    // horizontal mapping: 222 items = 3 col-groups x 74 rows, single wave
    const int hg  = (tid >= 148) ? 2 : (tid >= 74 ? 1 : 0);
    const int hr  = tid - hg * 74;
    const int hj0 = hg * 11;

    float lsum = 0.f;

    for (int c = 0; c < NCH; c++) {
        // ---------- per-channel load ----------
        if (interior)
            load_interior(img1, img2, sxyF, c, row0, col0, wid, lane);
        else
            load_border(img1, img2, sxyF, c, row0, col0, wid, lane);
        __syncthreads();

        // ---------- horizontal pass: uniform 11-wide, single full wave --------
        // group 2 computes 11 outputs but stores only 10 (col 32 discarded;
        // its window reads the never-written pitch word col 42, which only
        // feeds the discarded accumulator).
        if (tid < 222) {
            const ull* puv = (const ull*)sxyF + hr * PPX + hj0;

            ull auv[11], ass[11];
            #pragma unroll
            for (int o = 0; o < 11; o++) { auv[o] = 0; ass[o] = 0; }

            #pragma unroll
            for (int t = 0; t < 21; t++) {        // 11 + KW - 1
                ull vuv = puv[t];
                ull vss = mul2(vuv, vuv);
                #pragma unroll
                for (int o = 0; o < 11; o++) {
                    int k = t - o;
                    if (k >= 0 && k < KW) {       // compile-time resolved
                        auv[o] = fma2(wwr[WIDX(k)], vuv, auv[o]);
                        ass[o] = fma2(wwr[WIDX(k)], vss, ass[o]);
                    }
                }
            }
            ulonglong2* dst = hP + hr * HP + hj0;
            #pragma unroll
            for (int o = 0; o < 11; o++) {
                if (o < 10 || hg < 2)
                    dst[o] = make_ulonglong2(auv[o], ass[o]);   // STS.128, no movs
            }
        }
        __syncthreads();   // sxy reads done; h writes visible

        // ---------- vertical pass: exact single wave (32 cols x 8 warps) ------
        {
            int tx  = lane;                       // column 0..31
            int ty0 = wid << 3;                   // stack base row 0..56
            ull aU[8], aS[8];
            #pragma unroll
            for (int o = 0; o < 8; o++) { aU[o] = 0; aS[o] = 0; }

            #pragma unroll
            for (int t = 0; t < 18; t++) {
                int r = ty0 + t;
                ulonglong2 hv = hP[r * HP + tx];  // LDS.128 straight into pairs
                #pragma unroll
                for (int o = 0; o < 8; o++) {
                    int k = t - o;
                    if (k >= 0 && k < KW) {
                        aU[o] = fma2(wwr[WIDX(k)], hv.x, aU[o]);
                        aS[o] = fma2(wwr[WIDX(k)], hv.y, aS[o]);
                    }
                }
            }
            #pragma unroll
            for (int o = 0; o < 8; o++) {
                float2 uv = unpack2(aU[o]);      // U = mu1+mu2, V = mu1-mu2
                float2 ss = unpack2(aS[o]);      // Su = E[u^2], Sv = E[v^2]
                float U2 = uv.x * uv.x;
                float V2 = uv.y * uv.y;
                float A  = ss.x - U2;            // = s1+s2+2*s12 (x2 scale)
                float B  = ss.y - V2;            // = s1+s2-2*s12 (x2 scale)
                float num = fmaf(0.5f, U2 - V2, C1) * fmaf(0.5f, A - B, C2);
                float den = fmaf(0.5f, U2 + V2, C1) * fmaf(0.5f, A + B, C2);
                lsum += __fdividef(num, den);
            }
        }
        __syncthreads();   // h reads done before next channel overwrites sxy/h
    }

    // ---------- block reduction (8 warps) ----------
    #pragma unroll
    for (int s = 16; s > 0; s >>= 1)
        lsum += __shfl_xor_sync(0xffffffffu, lsum, s);
    __shared__ float red[8];
    if (lane == 0) red[wid] = lsum;
    __syncthreads();
    if (tid == 0) {
        float bs = 0.f;
        #pragma unroll
        for (int i = 0; i < 8; i++) bs += red[i];
        g_partial[blockIdx.y * GX + blockIdx.x] = bs;
    }

    // ---------- last-block finalize (no second launch) ----------
    __shared__ bool amLast;
    __threadfence();
    if (tid == 0) {
        unsigned int n = atomicAdd(&g_flag, 1u);
        amLast = (n == (unsigned)(NBLK - 1));
    }
    __syncthreads();
    if (amLast) {
        double s = 0.0;
        for (int i = tid; i < NBLK; i += NTHREADS)
            s += (double)g_partial[i];
        #pragma unroll
        for (int sft = 16; sft > 0; sft >>= 1)
            s += __shfl_xor_sync(0xffffffffu, s, sft);
        __shared__ double rd[8];
        if (lane == 0) rd[wid] = s;
        __syncthreads();
        if (tid == 0) {
            double t = 0.0;
            #pragma unroll
            for (int i = 0; i < 8; i++) t += rd[i];
            out[0] = (float)(1.0 - t / ((double)IMH * IMW * NCH));
            g_flag = 0;                 // reset for next graph replay
        }
    }
}

extern "C" void kernel_launch(void* const* d_in, const int* in_sizes, int n_in,
                              void* d_out, int out_size)
{
    const float* img1 = (const float*)d_in[0];
    const float* img2 = (const float*)d_in[1];
    const float* win  = (const float*)d_in[2];
    float* out = (float*)d_out;
    (void)in_sizes; (void)n_in; (void)out_size;

    const size_t SMEM = (size_t)SMEM_FLOATS * sizeof(float);   // 64528 B
    cudaFuncSetAttribute(ssim_tile_kernel,
                         cudaFuncAttributeMaxDynamicSharedMemorySize, (int)SMEM);

    dim3 grid(GX, GY);
    ssim_tile_kernel<<<grid, NTHREADS, SMEM>>>(img1, img2, win, out);
}

// round 16
// speedup vs baseline: 1.1654x; 1.0427x over previous
#include <cuda_runtime.h>

typedef unsigned long long ull;

#define TSX     32          // tile width
#define TSY     64          // tile height
#define HALO    5
#define KW      11
#define RNX     42          // TSX + 2*HALO
#define RNY     74          // TSY + 2*HALO
#define PPX     43          // sxy pitch in (u,v) pairs (ull)
#define HP      33          // h-buffer pitch in float4
#define IMH     2048
#define IMW     2048
#define NCH     3
#define NTHREADS 256
#define GX      64          // 2048 / TSX
#define GY      32          // 2048 / TSY
#define NBLK    (GX*GY)

#define C1 1.0e-4f
#define C2 9.0e-4f

// per-channel smem layout (floats)
#define OFS_SXY  0                              // RNY*PPX ull = 6364 floats
#define OFS_H    (RNY*PPX*2)                    // 6364
#define SMEM_FLOATS (OFS_H + RNY*HP*4)          // +9768 = 16132 (64528 B)

#define WIDX(k) ((k) <= 5 ? (k) : (10 - (k)))   // symmetric Gaussian taps

__device__ float g_partial[NBLK];
__device__ unsigned int g_flag;   // zero-init; last block resets it

__device__ __forceinline__ ull pack2(float lo, float hi) {
    ull r; asm("mov.b64 %0,{%1,%2};" : "=l"(r) : "f"(lo), "f"(hi)); return r;
}
__device__ __forceinline__ float2 unpack2(ull v) {
    float2 r; asm("mov.b64 {%0,%1},%2;" : "=f"(r.x), "=f"(r.y) : "l"(v)); return r;
}
__device__ __forceinline__ ull fma2(ull a, ull b, ull c) {
    ull d; asm("fma.rn.f32x2 %0,%1,%2,%3;" : "=l"(d) : "l"(a), "l"(b), "l"(c)); return d;
}
__device__ __forceinline__ ull mul2(ull a, ull b) {
    ull d; asm("mul.rn.f32x2 %0,%1,%2;" : "=l"(d) : "l"(a), "l"(b)); return d;
}

// -------- load: warp-per-row, division-free; interior CTAs skip all checks ---
__device__ __forceinline__ void load_interior(
    const float* __restrict__ img1, const float* __restrict__ img2,
    float* __restrict__ sxyF, int c, int row0, int col0, int wid, int lane)
{
    const float* b1 = img1 + (row0 * IMW + col0) * NCH + c;
    const float* b2 = img2 + (row0 * IMW + col0) * NCH + c;
    for (int r = wid; r < RNY; r += 8) {
        int roff = r * (IMW * NCH);
        float x = b1[roff + lane * NCH];
        float y = b2[roff + lane * NCH];
        ((float2*)sxyF)[r * PPX + lane] = make_float2(x + y, x - y);
        if (lane < RNX - 32) {
            int p = 32 + lane;
            float x2 = b1[roff + p * NCH];
            float y2 = b2[roff + p * NCH];
            ((float2*)sxyF)[r * PPX + p] = make_float2(x2 + y2, x2 - y2);
        }
    }
}

__device__ __forceinline__ void load_border(
    const float* __restrict__ img1, const float* __restrict__ img2,
    float* __restrict__ sxyF, int c, int row0, int col0, int wid, int lane)
{
    for (int r = wid; r < RNY; r += 8) {
        int gr = row0 + r;
        bool rok = (gr >= 0 && gr < IMH);
        #pragma unroll
        for (int s = 0; s < 2; s++) {
            int p = s * 32 + lane;
            if (p < RNX) {
                int gc = col0 + p;
                float v1 = 0.f, v2 = 0.f;
                if (rok && gc >= 0 && gc < IMW) {
                    int off = (gr * IMW + gc) * NCH + c;
                    v1 = img1[off];
                    v2 = img2[off];
                }
                ((float2*)sxyF)[r * PPX + p] = make_float2(v1 + v2, v1 - v2);
            }
        }
    }
}

__global__ __launch_bounds__(NTHREADS, 3) void ssim_tile_kernel(
    const float* __restrict__ img1,
    const float* __restrict__ img2,
    const float* __restrict__ window,
    float* __restrict__ out)
{
    extern __shared__ float smem[];
    float* sxyF = smem + OFS_SXY;                // (u,v) pairs, one channel
    float* hF   = smem + OFS_H;                  // (U,V,Su,Sv) float4 per column

    const int tid  = threadIdx.x;
    const int wid  = tid >> 5;
    const int lane = tid & 31;

    // ---- separable taps (symmetric): g_k = w2d[5][k] / sqrt(w2d[5][5]), k<=5
    ull wwr[6];
    {
        float g5 = sqrtf(window[5 * KW + 5]);
        #pragma unroll
        for (int k = 0; k < 6; k++) {
            float w = window[5 * KW + k] / g5;
            wwr[k] = pack2(w, w);
        }
    }

    const int bid  = (int)(blockIdx.y * GX + blockIdx.x);
    const int row0 = (int)blockIdx.y * TSY - HALO;
    const int col0 = (int)blockIdx.x * TSX - HALO;
    const bool interior = (row0 >= 0) && (row0 + RNY <= IMH) &&
                          (col0 >= 0) && (col0 + RNX <= IMW);

    // channel-order stagger: co-resident CTAs rotate their channel sequence so
    // fma-bound conv phases overlap neighbours' LDG-bound load phases
    const int coff = bid % NCH;

    // horizontal mapping: 222 items = 3 col-groups x 74 rows, single wave
    const int hg  = (tid >= 148) ? 2 : (tid >= 74 ? 1 : 0);
    const int hr  = tid - hg * 74;
    const int hj0 = hg * 11;

    float lsum = 0.f;

    for (int ci = 0; ci < NCH; ci++) {
        int c = ci + coff; if (c >= NCH) c -= NCH;

        // ---------- per-channel load ----------
        if (interior)
            load_interior(img1, img2, sxyF, c, row0, col0, wid, lane);
        else
            load_border(img1, img2, sxyF, c, row0, col0, wid, lane);
        __syncthreads();

        // ---------- horizontal pass: uniform 11-wide, single full wave --------
        // group 2 computes 11 outputs but stores only 10 (col 32 discarded;
        // its window reads the never-written pitch word col 42, which only
        // feeds the discarded accumulator).
        if (tid < 222) {
            const ull* puv = (const ull*)sxyF + hr * PPX + hj0;

            ull auv[11], ass[11];
            #pragma unroll
            for (int o = 0; o < 11; o++) { auv[o] = 0; ass[o] = 0; }

            #pragma unroll
            for (int t = 0; t < 21; t++) {        // 11 + KW - 1
                ull vuv = puv[t];
                ull vss = mul2(vuv, vuv);
                #pragma unroll
                for (int o = 0; o < 11; o++) {
                    int k = t - o;
                    if (k >= 0 && k < KW) {       // compile-time resolved
                        auv[o] = fma2(wwr[WIDX(k)], vuv, auv[o]);
                        ass[o] = fma2(wwr[WIDX(k)], vss, ass[o]);
                    }
                }
            }
            float4* dst = (float4*)hF + hr * HP + hj0;
            #pragma unroll
            for (int o = 0; o < 11; o++) {
                if (o < 10 || hg < 2) {
                    float2 a = unpack2(auv[o]);
                    float2 b = unpack2(ass[o]);
                    dst[o] = make_float4(a.x, a.y, b.x, b.y);
                }
            }
        }
        __syncthreads();   // sxy reads done; h writes visible

        // ---------- vertical pass: exact single wave (32 cols x 8 warps) ------
        {
            int tx  = lane;                       // column 0..31
            int ty0 = wid << 3;                   // stack base row 0..56
            ull aU[8], aS[8];
            #pragma unroll
            for (int o = 0; o < 8; o++) { aU[o] = 0; aS[o] = 0; }

            #pragma unroll
            for (int t = 0; t < 18; t++) {
                int r = ty0 + t;
                float4 h = ((const float4*)hF)[r * HP + tx];
                ull huv = pack2(h.x, h.y);
                ull hss = pack2(h.z, h.w);
                #pragma unroll
                for (int o = 0; o < 8; o++) {
                    int k = t - o;
                    if (k >= 0 && k < KW) {
                        aU[o] = fma2(wwr[WIDX(k)], huv, aU[o]);
                        aS[o] = fma2(wwr[WIDX(k)], hss, aS[o]);
                    }
                }
            }
            #pragma unroll
            for (int o = 0; o < 8; o++) {
                float2 uv = unpack2(aU[o]);      // U = mu1+mu2, V = mu1-mu2
                float2 ss = unpack2(aS[o]);      // Su = E[u^2], Sv = E[v^2]
                float U2 = uv.x * uv.x;
                float V2 = uv.y * uv.y;
                float A  = ss.x - U2;            // = s1+s2+2*s12 (x2 scale)
                float B  = ss.y - V2;            // = s1+s2-2*s12 (x2 scale)
                float num = fmaf(0.5f, U2 - V2, C1) * fmaf(0.5f, A - B, C2);
                float den = fmaf(0.5f, U2 + V2, C1) * fmaf(0.5f, A + B, C2);
                lsum += __fdividef(num, den);
            }
        }
        __syncthreads();   // h reads done before next channel overwrites sxy/h
    }

    // ---------- block reduction (8 warps) ----------
    #pragma unroll
    for (int s = 16; s > 0; s >>= 1)
        lsum += __shfl_xor_sync(0xffffffffu, lsum, s);
    __shared__ float red[8];
    if (lane == 0) red[wid] = lsum;
    __syncthreads();
    if (tid == 0) {
        float bs = 0.f;
        #pragma unroll
        for (int i = 0; i < 8; i++) bs += red[i];
        g_partial[bid] = bs;
    }

    // ---------- last-block finalize (no second launch) ----------
    __shared__ bool amLast;
    __threadfence();
    if (tid == 0) {
        unsigned int n = atomicAdd(&g_flag, 1u);
        amLast = (n == (unsigned)(NBLK - 1));
    }
    __syncthreads();
    if (amLast) {
        double s = 0.0;
        for (int i = tid; i < NBLK; i += NTHREADS)
            s += (double)g_partial[i];
        #pragma unroll
        for (int sft = 16; sft > 0; sft >>= 1)
            s += __shfl_xor_sync(0xffffffffu, s, sft);
        __shared__ double rd[8];
        if (lane == 0) rd[wid] = s;
        __syncthreads();
        if (tid == 0) {
            double t = 0.0;
            #pragma unroll
            for (int i = 0; i < 8; i++) t += rd[i];
            out[0] = (float)(1.0 - t / ((double)IMH * IMW * NCH));
            g_flag = 0;                 // reset for next graph replay
        }
    }
}

extern "C" void kernel_launch(void* const* d_in, const int* in_sizes, int n_in,
                              void* d_out, int out_size)
{
    const float* img1 = (const float*)d_in[0];
    const float* img2 = (const float*)d_in[1];
    const float* win  = (const float*)d_in[2];
    float* out = (float*)d_out;
    (void)in_sizes; (void)n_in; (void)out_size;

    const size_t SMEM = (size_t)SMEM_FLOATS * sizeof(float);   // 64528 B
    cudaFuncSetAttribute(ssim_tile_kernel,
                         cudaFuncAttributeMaxDynamicSharedMemorySize, (int)SMEM);

    dim3 grid(GX, GY);
    ssim_tile_kernel<<<grid, NTHREADS, SMEM>>>(img1, img2, win, out);
}